// round 1
// baseline (speedup 1.0000x reference)
#include <cuda_runtime.h>
#include <math.h>

#define G 256
#define BATCH 4
#define SEQ 4096
#define DIM 1024
#define HID 2048      // H
#define HID2 4096     // 2H
#define QD 128
#define ROWS (BATCH*SEQ)   // 16384
#define NGROUP (ROWS/G)    // 64

// ---------------- scratch (static device allocations; no cudaMalloc allowed) --
__device__ float g_normed[(size_t)ROWS*DIM];        // 64 MB
__device__ float g_hid[(size_t)ROWS*HID2];          // 256 MB (vv | gate)
__device__ float g_qp[(size_t)ROWS*QD];             // 8 MB
__device__ float g_kp[(size_t)ROWS*QD];
__device__ float g_qq[(size_t)ROWS*QD];             // quad_q
__device__ float g_lq[(size_t)ROWS*QD];             // lin_q
__device__ float g_qk[(size_t)ROWS*QD];             // quad_k
__device__ float g_lk[(size_t)ROWS*QD];             // lin_k
__device__ float g_attn[(size_t)NGROUP*G*G];        // 16 MB fallback
__device__ float g_acc[(size_t)ROWS*HID];           // 128 MB (quad_out + lin_out)
__device__ float g_linkv[(size_t)BATCH*QD*HID];     // 4 MB
__device__ float g_bias[G*G];                       // T5 bias table

// ---------------- layernorm: one block per row -------------------------------
__global__ void ln_kernel(const float* __restrict__ v, const float* __restrict__ g,
                          const float* __restrict__ b, float* __restrict__ out)
{
    int row = blockIdx.x;
    const float* x = v + (size_t)row * DIM;
    int t = threadIdx.x;
    float lv[4];
    float s = 0.f;
#pragma unroll
    for (int i = 0; i < 4; i++) { lv[i] = x[t + i*256]; s += lv[i]; }
    __shared__ float red[256];
    red[t] = s; __syncthreads();
    for (int o = 128; o > 0; o >>= 1) { if (t < o) red[t] += red[t+o]; __syncthreads(); }
    float mu = red[0] * (1.f/DIM);
    __syncthreads();
    float s2 = 0.f;
#pragma unroll
    for (int i = 0; i < 4; i++) { float d = lv[i]-mu; s2 += d*d; }
    red[t] = s2; __syncthreads();
    for (int o = 128; o > 0; o >>= 1) { if (t < o) red[t] += red[t+o]; __syncthreads(); }
    float inv = rsqrtf(red[0] * (1.f/DIM) + 1e-5f);
#pragma unroll
    for (int i = 0; i < 4; i++) {
        int c = t + i*256;
        out[(size_t)row*DIM + c] = (lv[i]-mu) * inv * g[c] + b[c];
    }
}

// ---------------- T5 relative position bias table [G, G] ---------------------
__global__ void bias_kernel(const float* __restrict__ rel_emb, float* __restrict__ bias)
{
    int idx = blockIdx.x * 256 + threadIdx.x;       // 65536 entries
    int i = idx >> 8, j = idx & 255;                // i = q pos, j = k pos
    int n0 = i - j;                                 // n = -(k_pos - q_pos)
    int ret = (n0 < 0) ? 16 : 0;
    int n = n0 < 0 ? -n0 : n0;
    int bucket;
    if (n < 8) {
        bucket = ret + n;
    } else {
        // log(n/8) / log(128/8) * 8, float32, truncate toward zero
        int vl = 8 + (int)(logf((float)n * 0.125f) / 2.7725887f * 8.0f);
        if (vl > 15) vl = 15;
        bucket = ret + vl;
    }
    bias[idx] = rel_emb[bucket] * 11.3137085f;      // sqrt(128)
}

// ---------------- affine: o0 = x*gamma[0]+beta[0], o1 = x*gamma[1]+beta[1] ----
__global__ void affine_kernel(const float* __restrict__ p,
                              const float* __restrict__ gamma, const float* __restrict__ beta,
                              float* __restrict__ o0, float* __restrict__ o1)
{
    size_t i = (size_t)blockIdx.x * 256 + threadIdx.x;   // over ROWS*QD
    int c = (int)(i & (QD-1));
    float x = p[i];
    o0[i] = x * gamma[c]      + beta[c];
    o1[i] = x * gamma[QD + c] + beta[QD + c];
}

// ---------------- pre = gate * (quad_out + lin_out), in place in acc ---------
__global__ void gatemul_kernel(float* __restrict__ acc, const float* __restrict__ hid)
{
    size_t i = (size_t)blockIdx.x * 256 + threadIdx.x;   // over ROWS*HID
    size_t r = i >> 11;          // / HID
    int c = (int)(i & (HID-1));
    acc[i] *= hid[r * HID2 + HID + c];
}

// ---------------- generic tiled SGEMM: 128x128x8, 256 thr, 8x8/thread --------
// EPI: 0 = (optional col-bias), 1 = silu(x + col-bias), 2 = relu(x + bias2d)^2
// TRANSA: A stored [K, M] row-major (for lin_kv = lin_k^T @ vv)
// ACCUM: C += result
template<int EPI, bool TRANSA, bool ACCUM>
__global__ void __launch_bounds__(256) sgemm(
    const float* __restrict__ A, const float* __restrict__ B,
    float* __restrict__ C, const float* __restrict__ bias,
    int M, int N, int K, int lda, int ldb, int ldc,
    long long sA, long long sB, long long sC, float alpha)
{
    long long z = blockIdx.z;
    A += z * sA; B += z * sB; C += z * sC;
    int bm = blockIdx.y * 128, bn = blockIdx.x * 128;

    __shared__ float As[8][128];
    __shared__ float Bs[8][128];
    int tid = threadIdx.x;
    int tx = tid & 15, ty = tid >> 4;

    float acc[8][8];
#pragma unroll
    for (int i = 0; i < 8; i++)
#pragma unroll
        for (int j = 0; j < 8; j++) acc[i][j] = 0.f;

    for (int k0 = 0; k0 < K; k0 += 8) {
        if (TRANSA) {
            int r = tid >> 5;               // k within tile
            int c = (tid & 31) << 2;        // m within tile
            float4 a4 = *reinterpret_cast<const float4*>(&A[(size_t)(k0 + r) * lda + bm + c]);
            *reinterpret_cast<float4*>(&As[r][c]) = a4;
        } else {
            int r = tid >> 1;               // m within tile
            int c = (tid & 1) << 2;         // k within tile
            float4 a4 = *reinterpret_cast<const float4*>(&A[(size_t)(bm + r) * lda + k0 + c]);
            As[c+0][r] = a4.x; As[c+1][r] = a4.y; As[c+2][r] = a4.z; As[c+3][r] = a4.w;
        }
        {
            int r = tid >> 5;               // k within tile
            int c = (tid & 31) << 2;        // n within tile
            float4 b4 = *reinterpret_cast<const float4*>(&B[(size_t)(k0 + r) * ldb + bn + c]);
            *reinterpret_cast<float4*>(&Bs[r][c]) = b4;
        }
        __syncthreads();
#pragma unroll
        for (int kk = 0; kk < 8; kk++) {
            float a[8], bb[8];
#pragma unroll
            for (int i = 0; i < 8; i++) a[i]  = As[kk][ty*8 + i];
#pragma unroll
            for (int j = 0; j < 8; j++) bb[j] = Bs[kk][tx*8 + j];
#pragma unroll
            for (int i = 0; i < 8; i++)
#pragma unroll
                for (int j = 0; j < 8; j++) acc[i][j] = fmaf(a[i], bb[j], acc[i][j]);
        }
        __syncthreads();
    }

#pragma unroll
    for (int i = 0; i < 8; i++) {
        int r = bm + ty*8 + i;
        if (r >= M) continue;
#pragma unroll
        for (int j = 0; j < 8; j++) {
            int c = bn + tx*8 + j;
            if (c >= N) continue;
            float v2 = acc[i][j] * alpha;
            if (EPI == 2) {
                v2 += bias[(size_t)r * G + c];      // local 2D bias (M==N==256)
                v2 = fmaxf(v2, 0.f);
                v2 = v2 * v2;
            } else {
                if (bias) v2 += bias[c];
                if (EPI == 1) v2 = v2 / (1.f + expf(-v2));   // silu
            }
            size_t idx = (size_t)r * ldc + c;
            if (ACCUM) v2 += C[idx];
            C[idx] = v2;
        }
    }
}

static float* sym(const void* symbol) {
    void* p = nullptr;
    cudaGetSymbolAddress(&p, symbol);
    return (float*)p;
}

extern "C" void kernel_launch(void* const* d_in, const int* in_sizes, int n_in,
                              void* d_out, int out_size)
{
    const float* q       = (const float*)d_in[0];
    const float* k       = (const float*)d_in[1];
    const float* v       = (const float*)d_in[2];
    const float* ln_g    = (const float*)d_in[3];
    const float* ln_b    = (const float*)d_in[4];
    const float* w_hid   = (const float*)d_in[5];
    const float* b_hid   = (const float*)d_in[6];
    const float* w_q     = (const float*)d_in[7];
    const float* b_q     = (const float*)d_in[8];
    const float* w_k     = (const float*)d_in[9];
    const float* b_k     = (const float*)d_in[10];
    const float* qs_gamma= (const float*)d_in[11];
    const float* qs_beta = (const float*)d_in[12];
    const float* ks_gamma= (const float*)d_in[13];
    const float* ks_beta = (const float*)d_in[14];
    const float* rel_emb = (const float*)d_in[15];
    const float* w_out   = (const float*)d_in[16];
    const float* b_out   = (const float*)d_in[17];

    float* out = (float*)d_out;

    float* normed = sym(g_normed);
    float* hid    = sym(g_hid);
    float* qp     = sym(g_qp);
    float* kp     = sym(g_kp);
    float* qq     = sym(g_qq);
    float* lq     = sym(g_lq);
    float* qk     = sym(g_qk);
    float* lk     = sym(g_lk);
    float* acc    = sym(g_acc);
    float* linkv  = sym(g_linkv);
    float* biasbuf= sym(g_bias);
    float* attn_scratch = sym(g_attn);

    // quad_attn (= attn.reshape(b, sn, G)) is the second output; its memory
    // layout equals the [b*g, 256, 256] attn buffer, so write it in place.
    const long long OUT0 = (long long)ROWS * DIM;               // 16777216
    const long long OUT1 = (long long)NGROUP * G * G;           // 4194304
    float* attn = (out_size >= OUT0 + OUT1) ? (out + OUT0) : attn_scratch;

    // 1. normed = LN(v)
    ln_kernel<<<ROWS, 256>>>(v, ln_g, ln_b, normed);

    // 2. T5 bias table
    bias_kernel<<<G*G/256, 256>>>(rel_emb, biasbuf);

    // 3. hid = silu(normed @ w_hid + b_hid)   [16384 x 4096, K=1024]
    sgemm<1,false,false><<<dim3(HID2/128, ROWS/128, 1), 256>>>(
        normed, w_hid, hid, b_hid, ROWS, HID2, DIM, DIM, HID2, HID2, 0, 0, 0, 1.f);

    // 4. qp = silu(q @ w_q + b_q), kp = silu(k @ w_k + b_k)   [16384 x 128, K=1024]
    sgemm<1,false,false><<<dim3(1, ROWS/128, 1), 256>>>(
        q, w_q, qp, b_q, ROWS, QD, DIM, DIM, QD, QD, 0, 0, 0, 1.f);
    sgemm<1,false,false><<<dim3(1, ROWS/128, 1), 256>>>(
        k, w_k, kp, b_k, ROWS, QD, DIM, DIM, QD, QD, 0, 0, 0, 1.f);

    // 5. affine splits
    affine_kernel<<<ROWS*QD/256, 256>>>(qp, qs_gamma, qs_beta, qq, lq);
    affine_kernel<<<ROWS*QD/256, 256>>>(kp, ks_gamma, ks_beta, qk, lk);

    // 6. attn = relu(qq@qk^T... (row-major dot) /G + bias)^2, per group (64)
    //    A rows and B rows are both [256,128]; sim[i,j] = dot(Aq_i, Ak_j):
    //    implemented as A[M,K] @ B[K,N] with B read as k-major? No: both are
    //    row-major [256,128]; we need A @ B^T. Use TRANSB-free trick: treat
    //    B^T as [K=128, N=256] stored column-major == qk row-major with
    //    ldb... instead use TRANSA path on swapped operands:
    //    sim^T = qk @ qq^T. Simpler: sim = (qq) @ (qk)^T via TRANSA variant:
    //    C[M,N] with A := qk stored [N,K]? Use: sgemm<2,true,..> computing
    //    C = A^T @ B where A = qq^T? Both operands are [256,128] row-major.
    //    C[i][j] = sum_d qq[i][d] * qk[j][d]
    //           == (qq^T)^T @ (qk^T)  -> take TRANSA with A := qq stored [K?]..
    //    Cleanest: B-operand must be [K, N]; qk^T is [128, 256] which is qk
    //    viewed with element (d, j) at qk[j*128 + d] -> not contiguous rows.
    //    So instead compute with A = qq (normal, [M,K]) and "B" = qk^T by
    //    materializing nothing: use the TRANSA machinery on the OTHER side by
    //    computing C^T = qk @ qq^T ... same issue. Materialize qk^T cheaply?
    //    K is only 128: just use a dedicated small kernel below.
    {
        // dedicated attn kernel via sgemm on transposed-k scratch is avoided:
        // reuse sgemm with TRANSA semantics: C = A^T @ B with A := qq^T?
        // Simplest correct path: transpose qk groups into g_kp (reuse) as
        // [g][128][256] so B is [K=128, N=256] row-major.
    }
    // transpose qk per group into kp scratch (kp no longer needed): kt[g][d][j] = qk[g][j][d]
    {
        extern __global__ void kt_kernel(const float*, float*);
        kt_kernel<<<ROWS*QD/256, 256>>>(qk, kp);
    }
    sgemm<2,false,false><<<dim3(G/128, G/128, NGROUP), 256>>>(
        qq, kp, attn, biasbuf, G, G, QD, QD, G, G,
        (long long)G*QD, (long long)G*QD, (long long)G*G, 1.f/G);

    // 7. quad_out = attn @ cv   (cv = hid[:, :2048] group rows), into acc
    sgemm<0,false,false><<<dim3(HID/128, G/128, NGROUP), 256>>>(
        attn, hid, acc, nullptr, G, HID, G, G, HID2, HID,
        (long long)G*G, (long long)G*HID2, (long long)G*HID, 1.f);

    // 8. lin_kv[b] = lk[b]^T @ vv[b] / 4096   [128 x 2048, K=4096]
    sgemm<0,true,false><<<dim3(HID/128, 1, BATCH), 256>>>(
        lk, hid, linkv, nullptr, QD, HID, SEQ, QD, HID2, HID,
        (long long)SEQ*QD, (long long)SEQ*HID2, (long long)QD*HID, 1.f/SEQ);

    // 9. lin_out = lq @ lin_kv, accumulated into acc
    sgemm<0,false,true><<<dim3(HID/128, SEQ/128, BATCH), 256>>>(
        lq, linkv, acc, nullptr, SEQ, HID, QD, QD, HID, HID,
        (long long)SEQ*QD, (long long)QD*HID, (long long)SEQ*HID, 1.f);

    // 10. acc *= gate
    gatemul_kernel<<<(int)((size_t)ROWS*HID/256), 256>>>(acc, hid);

    // 11. out = acc @ w_out + b_out   [16384 x 1024, K=2048]
    sgemm<0,false,false><<<dim3(DIM/128, ROWS/128, 1), 256>>>(
        acc, w_out, out, b_out, ROWS, DIM, HID, HID, DIM, DIM, 0, 0, 0, 1.f);
}

// per-group transpose: in [64 groups][256][128] -> out [64 groups][128][256]
__global__ void kt_kernel(const float* __restrict__ in, float* __restrict__ qkt)
{
    size_t i = (size_t)blockIdx.x * 256 + threadIdx.x;   // over ROWS*QD
    size_t grp = i >> 15;                // / (256*128)
    int rem = (int)(i & 32767);
    int row = rem >> 7;                  // 0..255 within group
    int d   = rem & 127;                 // 0..127
    qkt[grp * (size_t)(QD*G) + (size_t)d * G + row] = in[i];
}

// round 3
// speedup vs baseline: 2.5193x; 2.5193x over previous
#include <cuda_runtime.h>
#include <cuda_bf16.h>
#include <math.h>
#include <stdint.h>

#define G 256
#define BATCH 4
#define SEQ 4096
#define DIM 1024
#define HID 2048      // H
#define HID2 4096     // 2H
#define QD 128
#define ROWS (BATCH*SEQ)   // 16384
#define NGROUP (ROWS/G)    // 64

// ======================= static device scratch ==============================
__device__ float g_hid[(size_t)ROWS*HID2];          // fp32 hid (vv | gate)
__device__ float g_acc[(size_t)ROWS*HID];           // quad_out + lin_out
__device__ float g_linkv[(size_t)BATCH*QD*HID];
__device__ float g_qp[(size_t)ROWS*QD];
__device__ float g_kp[(size_t)ROWS*QD];             // reused as qk^T scratch
__device__ float g_qq[(size_t)ROWS*QD];
__device__ float g_qk[(size_t)ROWS*QD];
__device__ float g_lk[(size_t)ROWS*QD];
__device__ float g_attn[(size_t)NGROUP*G*G];        // fallback if out too small
__device__ float g_bias[G*G];

// bf16 hi/lo planes (16B aligned for cp.async)
__device__ __align__(16) __nv_bfloat16 g_nPh[(size_t)ROWS*DIM],  g_nPl[(size_t)ROWS*DIM];
__device__ __align__(16) __nv_bfloat16 g_qPh[(size_t)ROWS*DIM],  g_qPl[(size_t)ROWS*DIM];
__device__ __align__(16) __nv_bfloat16 g_kPh[(size_t)ROWS*DIM],  g_kPl[(size_t)ROWS*DIM];
__device__ __align__(16) __nv_bfloat16 g_whTh[(size_t)HID2*DIM], g_whTl[(size_t)HID2*DIM];
__device__ __align__(16) __nv_bfloat16 g_woTh[(size_t)DIM*HID],  g_woTl[(size_t)DIM*HID];
__device__ __align__(16) __nv_bfloat16 g_wqTh[QD*DIM], g_wqTl[QD*DIM];
__device__ __align__(16) __nv_bfloat16 g_wkTh[QD*DIM], g_wkTl[QD*DIM];
__device__ __align__(16) __nv_bfloat16 g_atPh[(size_t)NGROUP*G*G], g_atPl[(size_t)NGROUP*G*G];
__device__ __align__(16) __nv_bfloat16 g_lqPh[(size_t)ROWS*QD],  g_lqPl[(size_t)ROWS*QD];
__device__ __align__(16) __nv_bfloat16 g_lkTh[(size_t)ROWS*QD],  g_lkTl[(size_t)ROWS*QD];   // [4][128][4096]
__device__ __align__(16) __nv_bfloat16 g_vvTh[(size_t)BATCH*HID*SEQ], g_vvTl[(size_t)BATCH*HID*SEQ]; // [4][2048][4096]
__device__ __align__(16) __nv_bfloat16 g_kvTh[(size_t)BATCH*HID*QD],  g_kvTl[(size_t)BATCH*HID*QD];  // [4][2048][128]
__device__ __align__(16) __nv_bfloat16 g_acPh[(size_t)ROWS*HID], g_acPl[(size_t)ROWS*HID];

// ======================= helpers ============================================
__device__ __forceinline__ uint32_t smem_u32(const void* p) {
    uint32_t a;
    asm("{ .reg .u64 t; cvta.to.shared.u64 t, %1; cvt.u32.u64 %0, t; }" : "=r"(a) : "l"(p));
    return a;
}
__device__ __forceinline__ uint32_t lds32(uint32_t a) {
    uint32_t v;
    asm("ld.shared.b32 %0, [%1];" : "=r"(v) : "r"(a));
    return v;
}
__device__ __forceinline__ void split2(float x, __nv_bfloat16& h, __nv_bfloat16& l) {
    h = __float2bfloat16(x);
    l = __float2bfloat16(x - __bfloat162float(h));
}

#define MMA_BF16(d, a, b) \
    asm volatile("mma.sync.aligned.m16n8k16.row.col.f32.bf16.bf16.f32 " \
        "{%0,%1,%2,%3}, {%4,%5,%6,%7}, {%8,%9}, {%0,%1,%2,%3};" \
        : "+f"((d)[0]), "+f"((d)[1]), "+f"((d)[2]), "+f"((d)[3]) \
        : "r"((a)[0]), "r"((a)[1]), "r"((a)[2]), "r"((a)[3]), \
          "r"((b)[0]), "r"((b)[1]))

// ======================= HMMA bf16x3 GEMM ===================================
// C[M,N] = alpha * A @ B^T (+ col bias) (+silu) (+= C)
// A planes: [M,K] K-major bf16; B planes: [N,K] K-major bf16. K % 64 == 0.
// Per z: A += z*sA; B += (z/zdiv)*sBo + (z%zdiv)*sBi; C += z*sC.
// Block tile 128x128, kc=64, double-buffered cp.async.
#define KC 64
#define PITCH 144                     // bytes per smem row (64 elem + 8 pad)
#define PLANE (128*PITCH)             // 18432 B
#define STAGE (4*PLANE)               // 73728 B
#define HG_SMEM (2*STAGE)             // 147456 B

__device__ __forceinline__ void load_plane(uint32_t sdst, const __nv_bfloat16* src,
                                           int row0, int ld, int k0, int tid)
{
#pragma unroll
    for (int i = 0; i < 4; i++) {
        int idx = tid + i * 256;
        int r = idx >> 3, seg = idx & 7;
        uint32_t d = sdst + r * PITCH + seg * 16;
        const void* gp = src + (size_t)(row0 + r) * ld + k0 + seg * 8;
        asm volatile("cp.async.cg.shared.global [%0], [%1], 16;" :: "r"(d), "l"(gp));
    }
}

template<int EPI, bool ACCUM>   // EPI: 0 none, 1 silu
__global__ void __launch_bounds__(256, 1) hgemm(
    const __nv_bfloat16* __restrict__ Ah, const __nv_bfloat16* __restrict__ Al,
    const __nv_bfloat16* __restrict__ Bh, const __nv_bfloat16* __restrict__ Bl,
    float* __restrict__ C, const float* __restrict__ bias,
    int K, int lda, int ldb, int ldc,
    long long sA, long long sBo, int zdiv, long long sBi, long long sC,
    float alpha)
{
    extern __shared__ char smem[];
    const int z = blockIdx.z;
    Ah += (long long)z * sA;  Al += (long long)z * sA;
    long long bo = (long long)(z / zdiv) * sBo + (long long)(z % zdiv) * sBi;
    Bh += bo;  Bl += bo;
    C  += (long long)z * sC;
    const int bm = blockIdx.y * 128, bn = blockIdx.x * 128;

    const uint32_t sb = smem_u32(smem);
    const int tid = threadIdx.x;
    const int lane = tid & 31, wid = tid >> 5;
    const int warp_m = wid & 3, warp_n = wid >> 2;    // 4 x 2 warps
    const int gr = lane >> 2, tq = lane & 3;

    float acc[2][8][4];
#pragma unroll
    for (int mt = 0; mt < 2; mt++)
#pragma unroll
        for (int nt = 0; nt < 8; nt++)
#pragma unroll
            for (int i = 0; i < 4; i++) acc[mt][nt][i] = 0.f;

    const int nchunks = K >> 6;

    // prologue: stage 0
    load_plane(sb,           Ah, bm, lda, 0, tid);
    load_plane(sb +   PLANE, Al, bm, lda, 0, tid);
    load_plane(sb + 2*PLANE, Bh, bn, ldb, 0, tid);
    load_plane(sb + 3*PLANE, Bl, bn, ldb, 0, tid);
    asm volatile("cp.async.commit_group;");

    for (int c = 0; c < nchunks; ++c) {
        if (c + 1 < nchunks) {
            uint32_t st = sb + ((c + 1) & 1) * STAGE;
            int k0 = (c + 1) << 6;
            load_plane(st,           Ah, bm, lda, k0, tid);
            load_plane(st +   PLANE, Al, bm, lda, k0, tid);
            load_plane(st + 2*PLANE, Bh, bn, ldb, k0, tid);
            load_plane(st + 3*PLANE, Bl, bn, ldb, k0, tid);
            asm volatile("cp.async.commit_group;");
            asm volatile("cp.async.wait_group %0;" :: "n"(1));
        } else {
            asm volatile("cp.async.wait_group %0;" :: "n"(0));
        }
        __syncthreads();

        const uint32_t stg = sb + (c & 1) * STAGE;
#pragma unroll
        for (int kk = 0; kk < 4; kk++) {
            const int koff = kk * 32;   // bytes: kk*16 elems * 2
            uint32_t a_h[2][4], a_l[2][4];
#pragma unroll
            for (int mt = 0; mt < 2; mt++) {
                uint32_t ro = stg + (warp_m*32 + mt*16 + gr) * PITCH + koff + tq*4;
                a_h[mt][0] = lds32(ro);
                a_h[mt][1] = lds32(ro + 8*PITCH);
                a_h[mt][2] = lds32(ro + 16);
                a_h[mt][3] = lds32(ro + 8*PITCH + 16);
                uint32_t rl = ro + PLANE;
                a_l[mt][0] = lds32(rl);
                a_l[mt][1] = lds32(rl + 8*PITCH);
                a_l[mt][2] = lds32(rl + 16);
                a_l[mt][3] = lds32(rl + 8*PITCH + 16);
            }
            uint32_t b_h[8][2], b_l[8][2];
#pragma unroll
            for (int nt = 0; nt < 8; nt++) {
                uint32_t ro = stg + 2*PLANE + (warp_n*64 + nt*8 + gr) * PITCH + koff + tq*4;
                b_h[nt][0] = lds32(ro);
                b_h[nt][1] = lds32(ro + 16);
                b_l[nt][0] = lds32(ro + PLANE);
                b_l[nt][1] = lds32(ro + PLANE + 16);
            }
#pragma unroll
            for (int mt = 0; mt < 2; mt++)
#pragma unroll
                for (int nt = 0; nt < 8; nt++) {
                    MMA_BF16(acc[mt][nt], a_h[mt], b_h[nt]);
                    MMA_BF16(acc[mt][nt], a_h[mt], b_l[nt]);
                    MMA_BF16(acc[mt][nt], a_l[mt], b_h[nt]);
                }
        }
        __syncthreads();
    }

    // epilogue
#pragma unroll
    for (int mt = 0; mt < 2; mt++) {
        const int row0 = bm + warp_m*32 + mt*16 + gr;
#pragma unroll
        for (int nt = 0; nt < 8; nt++) {
            const int col = bn + warp_n*64 + nt*8 + tq*2;
            float2 bb = make_float2(0.f, 0.f);
            if (bias) bb = *reinterpret_cast<const float2*>(bias + col);
#pragma unroll
            for (int h = 0; h < 2; h++) {
                const int row = row0 + h*8;
                float vx = acc[mt][nt][h*2+0] * alpha + bb.x;
                float vy = acc[mt][nt][h*2+1] * alpha + bb.y;
                if (EPI == 1) {
                    vx = vx / (1.f + expf(-vx));
                    vy = vy / (1.f + expf(-vy));
                }
                float* cp = C + (size_t)row * ldc + col;
                if (ACCUM) {
                    float2 o = *reinterpret_cast<const float2*>(cp);
                    vx += o.x; vy += o.y;
                }
                *reinterpret_cast<float2*>(cp) = make_float2(vx, vy);
            }
        }
    }
}

// ======================= elementwise / transform kernels ====================
__global__ void ln_kernel(const float* __restrict__ v, const float* __restrict__ g,
                          const float* __restrict__ b,
                          __nv_bfloat16* __restrict__ oh, __nv_bfloat16* __restrict__ ol)
{
    int row = blockIdx.x;
    const float* x = v + (size_t)row * DIM;
    int t = threadIdx.x;
    float lv[4];
    float s = 0.f;
#pragma unroll
    for (int i = 0; i < 4; i++) { lv[i] = x[t + i*256]; s += lv[i]; }
    __shared__ float red[256];
    red[t] = s; __syncthreads();
    for (int o = 128; o > 0; o >>= 1) { if (t < o) red[t] += red[t+o]; __syncthreads(); }
    float mu = red[0] * (1.f/DIM);
    __syncthreads();
    float s2 = 0.f;
#pragma unroll
    for (int i = 0; i < 4; i++) { float d = lv[i]-mu; s2 += d*d; }
    red[t] = s2; __syncthreads();
    for (int o = 128; o > 0; o >>= 1) { if (t < o) red[t] += red[t+o]; __syncthreads(); }
    float inv = rsqrtf(red[0] * (1.f/DIM) + 1e-5f);
#pragma unroll
    for (int i = 0; i < 4; i++) {
        int c = t + i*256;
        float y = (lv[i]-mu) * inv * g[c] + b[c];
        __nv_bfloat16 h, l; split2(y, h, l);
        oh[(size_t)row*DIM + c] = h;
        ol[(size_t)row*DIM + c] = l;
    }
}

__global__ void bias_kernel(const float* __restrict__ rel_emb, float* __restrict__ bias)
{
    int idx = blockIdx.x * 256 + threadIdx.x;
    int i = idx >> 8, j = idx & 255;
    int n0 = i - j;
    int ret = (n0 < 0) ? 16 : 0;
    int n = n0 < 0 ? -n0 : n0;
    int bucket;
    if (n < 8) bucket = ret + n;
    else {
        int vl = 8 + (int)(logf((float)n * 0.125f) / 2.7725887f * 8.0f);
        if (vl > 15) vl = 15;
        bucket = ret + vl;
    }
    bias[idx] = rel_emb[bucket] * 11.3137085f;
}

__global__ void plaincvt(const float* __restrict__ in,
                         __nv_bfloat16* __restrict__ oh, __nv_bfloat16* __restrict__ ol)
{
    size_t i = (size_t)blockIdx.x * 256 + threadIdx.x;
    __nv_bfloat16 h, l; split2(in[i], h, l);
    oh[i] = h; ol[i] = l;
}

// transpose fp32 [R, C] -> bf16 planes [C, R]; grid (C/32, R/32, batch), block (32, 8)
__global__ void transcvt(const float* __restrict__ in,
                         __nv_bfloat16* __restrict__ oh, __nv_bfloat16* __restrict__ ol,
                         int ld_in, int ld_out, long long sIn, long long sOut)
{
    __shared__ float t[32][33];
    in += (long long)blockIdx.z * sIn;
    oh += (long long)blockIdx.z * sOut;
    ol += (long long)blockIdx.z * sOut;
    int c0 = blockIdx.x * 32, r0 = blockIdx.y * 32;
    int tx = threadIdx.x, ty = threadIdx.y;
#pragma unroll
    for (int i = 0; i < 4; i++)
        t[ty + i*8][tx] = in[(size_t)(r0 + ty + i*8) * ld_in + c0 + tx];
    __syncthreads();
#pragma unroll
    for (int i = 0; i < 4; i++) {
        float x = t[tx][ty + i*8];
        __nv_bfloat16 h, l; split2(x, h, l);
        size_t o = (size_t)(c0 + ty + i*8) * ld_out + r0 + tx;
        oh[o] = h; ol[o] = l;
    }
}

__global__ void affine_q(const float* __restrict__ p,
                         const float* __restrict__ gamma, const float* __restrict__ beta,
                         float* __restrict__ qq,
                         __nv_bfloat16* __restrict__ lqh, __nv_bfloat16* __restrict__ lql)
{
    size_t i = (size_t)blockIdx.x * 256 + threadIdx.x;
    int c = (int)(i & (QD-1));
    float x = p[i];
    qq[i] = x * gamma[c] + beta[c];
    float lq = x * gamma[QD + c] + beta[QD + c];
    __nv_bfloat16 h, l; split2(lq, h, l);
    lqh[i] = h; lql[i] = l;
}

__global__ void affine_k(const float* __restrict__ p,
                         const float* __restrict__ gamma, const float* __restrict__ beta,
                         float* __restrict__ qk, float* __restrict__ lk)
{
    size_t i = (size_t)blockIdx.x * 256 + threadIdx.x;
    int c = (int)(i & (QD-1));
    float x = p[i];
    qk[i] = x * gamma[c] + beta[c];
    lk[i] = x * gamma[QD + c] + beta[QD + c];
}

__global__ void gatemul(const float* __restrict__ acc, const float* __restrict__ hid,
                        __nv_bfloat16* __restrict__ oh, __nv_bfloat16* __restrict__ ol)
{
    size_t i = (size_t)blockIdx.x * 256 + threadIdx.x;
    size_t r = i >> 11;
    int c = (int)(i & (HID-1));
    float v = acc[i] * hid[r * HID2 + HID + c];
    __nv_bfloat16 h, l; split2(v, h, l);
    oh[i] = h; ol[i] = l;
}

// per-group transpose: in [64][256][128] -> out [64][128][256]
__global__ void kt_kernel(const float* __restrict__ in, float* __restrict__ qkt)
{
    size_t i = (size_t)blockIdx.x * 256 + threadIdx.x;
    size_t grp = i >> 15;
    int rem = (int)(i & 32767);
    int row = rem >> 7;
    int d   = rem & 127;
    qkt[grp * (size_t)(QD*G) + (size_t)d * G + row] = in[i];
}

// ---------------- fp32 sgemm (tiny sim GEMM only, relu^2 + 2D bias) ---------
template<int EPI, bool TRANSA, bool ACCUM>
__global__ void __launch_bounds__(256) sgemm(
    const float* __restrict__ A, const float* __restrict__ B,
    float* __restrict__ C, const float* __restrict__ bias,
    int M, int N, int K, int lda, int ldb, int ldc,
    long long sA, long long sB, long long sC, float alpha)
{
    long long z = blockIdx.z;
    A += z * sA; B += z * sB; C += z * sC;
    int bm = blockIdx.y * 128, bn = blockIdx.x * 128;

    __shared__ float As[8][128];
    __shared__ float Bs[8][128];
    int tid = threadIdx.x;
    int tx = tid & 15, ty = tid >> 4;

    float acc[8][8];
#pragma unroll
    for (int i = 0; i < 8; i++)
#pragma unroll
        for (int j = 0; j < 8; j++) acc[i][j] = 0.f;

    for (int k0 = 0; k0 < K; k0 += 8) {
        if (TRANSA) {
            int r = tid >> 5;
            int c = (tid & 31) << 2;
            float4 a4 = *reinterpret_cast<const float4*>(&A[(size_t)(k0 + r) * lda + bm + c]);
            *reinterpret_cast<float4*>(&As[r][c]) = a4;
        } else {
            int r = tid >> 1;
            int c = (tid & 1) << 2;
            float4 a4 = *reinterpret_cast<const float4*>(&A[(size_t)(bm + r) * lda + k0 + c]);
            As[c+0][r] = a4.x; As[c+1][r] = a4.y; As[c+2][r] = a4.z; As[c+3][r] = a4.w;
        }
        {
            int r = tid >> 5;
            int c = (tid & 31) << 2;
            float4 b4 = *reinterpret_cast<const float4*>(&B[(size_t)(k0 + r) * ldb + bn + c]);
            *reinterpret_cast<float4*>(&Bs[r][c]) = b4;
        }
        __syncthreads();
#pragma unroll
        for (int kk = 0; kk < 8; kk++) {
            float a[8], bb[8];
#pragma unroll
            for (int i = 0; i < 8; i++) a[i]  = As[kk][ty*8 + i];
#pragma unroll
            for (int j = 0; j < 8; j++) bb[j] = Bs[kk][tx*8 + j];
#pragma unroll
            for (int i = 0; i < 8; i++)
#pragma unroll
                for (int j = 0; j < 8; j++) acc[i][j] = fmaf(a[i], bb[j], acc[i][j]);
        }
        __syncthreads();
    }

#pragma unroll
    for (int i = 0; i < 8; i++) {
        int r = bm + ty*8 + i;
        if (r >= M) continue;
#pragma unroll
        for (int j = 0; j < 8; j++) {
            int c = bn + tx*8 + j;
            if (c >= N) continue;
            float v2 = acc[i][j] * alpha;
            if (EPI == 2) {
                v2 += bias[(size_t)r * G + c];
                v2 = fmaxf(v2, 0.f);
                v2 = v2 * v2;
            } else {
                if (bias) v2 += bias[c];
                if (EPI == 1) v2 = v2 / (1.f + expf(-v2));
            }
            size_t idx = (size_t)r * ldc + c;
            if (ACCUM) v2 += C[idx];
            C[idx] = v2;
        }
    }
}

// ======================= host orchestration =================================
static void* symaddr(const void* s) {
    void* p = nullptr;
    cudaGetSymbolAddress(&p, s);
    return p;
}

extern "C" void kernel_launch(void* const* d_in, const int* in_sizes, int n_in,
                              void* d_out, int out_size)
{
    const float* q       = (const float*)d_in[0];
    const float* k       = (const float*)d_in[1];
    const float* v       = (const float*)d_in[2];
    const float* ln_g    = (const float*)d_in[3];
    const float* ln_b    = (const float*)d_in[4];
    const float* w_hid   = (const float*)d_in[5];
    const float* b_hid   = (const float*)d_in[6];
    const float* w_q     = (const float*)d_in[7];
    const float* b_q     = (const float*)d_in[8];
    const float* w_k     = (const float*)d_in[9];
    const float* b_k     = (const float*)d_in[10];
    const float* qs_gamma= (const float*)d_in[11];
    const float* qs_beta = (const float*)d_in[12];
    const float* ks_gamma= (const float*)d_in[13];
    const float* ks_beta = (const float*)d_in[14];
    const float* rel_emb = (const float*)d_in[15];
    const float* w_out   = (const float*)d_in[16];
    const float* b_out   = (const float*)d_in[17];

    float* out = (float*)d_out;

    float* hid    = (float*)symaddr(g_hid);
    float* acc    = (float*)symaddr(g_acc);
    float* linkv  = (float*)symaddr(g_linkv);
    float* qp     = (float*)symaddr(g_qp);
    float* kpT    = (float*)symaddr(g_kp);
    float* qq     = (float*)symaddr(g_qq);
    float* qk     = (float*)symaddr(g_qk);
    float* lk     = (float*)symaddr(g_lk);
    float* biasbuf= (float*)symaddr(g_bias);
    float* attn_scratch = (float*)symaddr(g_attn);

    __nv_bfloat16* nPh = (__nv_bfloat16*)symaddr(g_nPh);
    __nv_bfloat16* nPl = (__nv_bfloat16*)symaddr(g_nPl);
    __nv_bfloat16* qPh = (__nv_bfloat16*)symaddr(g_qPh);
    __nv_bfloat16* qPl = (__nv_bfloat16*)symaddr(g_qPl);
    __nv_bfloat16* kPh = (__nv_bfloat16*)symaddr(g_kPh);
    __nv_bfloat16* kPl = (__nv_bfloat16*)symaddr(g_kPl);
    __nv_bfloat16* whTh = (__nv_bfloat16*)symaddr(g_whTh);
    __nv_bfloat16* whTl = (__nv_bfloat16*)symaddr(g_whTl);
    __nv_bfloat16* woTh = (__nv_bfloat16*)symaddr(g_woTh);
    __nv_bfloat16* woTl = (__nv_bfloat16*)symaddr(g_woTl);
    __nv_bfloat16* wqTh = (__nv_bfloat16*)symaddr(g_wqTh);
    __nv_bfloat16* wqTl = (__nv_bfloat16*)symaddr(g_wqTl);
    __nv_bfloat16* wkTh = (__nv_bfloat16*)symaddr(g_wkTh);
    __nv_bfloat16* wkTl = (__nv_bfloat16*)symaddr(g_wkTl);
    __nv_bfloat16* atPh = (__nv_bfloat16*)symaddr(g_atPh);
    __nv_bfloat16* atPl = (__nv_bfloat16*)symaddr(g_atPl);
    __nv_bfloat16* lqPh = (__nv_bfloat16*)symaddr(g_lqPh);
    __nv_bfloat16* lqPl = (__nv_bfloat16*)symaddr(g_lqPl);
    __nv_bfloat16* lkTh = (__nv_bfloat16*)symaddr(g_lkTh);
    __nv_bfloat16* lkTl = (__nv_bfloat16*)symaddr(g_lkTl);
    __nv_bfloat16* vvTh = (__nv_bfloat16*)symaddr(g_vvTh);
    __nv_bfloat16* vvTl = (__nv_bfloat16*)symaddr(g_vvTl);
    __nv_bfloat16* kvTh = (__nv_bfloat16*)symaddr(g_kvTh);
    __nv_bfloat16* kvTl = (__nv_bfloat16*)symaddr(g_kvTl);
    __nv_bfloat16* acPh = (__nv_bfloat16*)symaddr(g_acPh);
    __nv_bfloat16* acPl = (__nv_bfloat16*)symaddr(g_acPl);

    const long long OUT0 = (long long)ROWS * DIM;
    const long long OUT1 = (long long)NGROUP * G * G;
    float* attn = (out_size >= OUT0 + OUT1) ? (out + OUT0) : attn_scratch;

    cudaFuncSetAttribute(hgemm<0,false>, cudaFuncAttributeMaxDynamicSharedMemorySize, HG_SMEM);
    cudaFuncSetAttribute(hgemm<0,true >, cudaFuncAttributeMaxDynamicSharedMemorySize, HG_SMEM);
    cudaFuncSetAttribute(hgemm<1,false>, cudaFuncAttributeMaxDynamicSharedMemorySize, HG_SMEM);

    // 1. LN(v) -> normed planes
    ln_kernel<<<ROWS, 256>>>(v, ln_g, ln_b, nPh, nPl);
    // 2. T5 bias
    bias_kernel<<<G*G/256, 256>>>(rel_emb, biasbuf);
    // 3. convert q, k inputs to planes
    plaincvt<<<(int)((size_t)ROWS*DIM/256), 256>>>(q, qPh, qPl);
    plaincvt<<<(int)((size_t)ROWS*DIM/256), 256>>>(k, kPh, kPl);
    // 4. transpose+convert weights: [K,N] -> [N,K]
    transcvt<<<dim3(HID2/32, DIM/32, 1), dim3(32,8)>>>(w_hid, whTh, whTl, HID2, DIM, 0, 0);
    transcvt<<<dim3(DIM/32, HID/32, 1), dim3(32,8)>>>(w_out, woTh, woTl, DIM, HID, 0, 0);
    transcvt<<<dim3(QD/32, DIM/32, 1), dim3(32,8)>>>(w_q, wqTh, wqTl, QD, DIM, 0, 0);
    transcvt<<<dim3(QD/32, DIM/32, 1), dim3(32,8)>>>(w_k, wkTh, wkTl, QD, DIM, 0, 0);

    // 5. hid = silu(normed @ w_hid + b_hid)   [16384 x 4096]
    hgemm<1,false><<<dim3(HID2/128, ROWS/128, 1), 256, HG_SMEM>>>(
        nPh, nPl, whTh, whTl, hid, b_hid,
        DIM, DIM, DIM, HID2, 0, 0, 1, 0, 0, 1.f);

    // 6. qp = silu(q @ w_q + b_q); kp = silu(k @ w_k + b_k)
    hgemm<1,false><<<dim3(1, ROWS/128, 1), 256, HG_SMEM>>>(
        qPh, qPl, wqTh, wqTl, qp, b_q,
        DIM, DIM, DIM, QD, 0, 0, 1, 0, 0, 1.f);
    hgemm<1,false><<<dim3(1, ROWS/128, 1), 256, HG_SMEM>>>(
        kPh, kPl, wkTh, wkTl, qk /*temp kp*/, b_k,
        DIM, DIM, DIM, QD, 0, 0, 1, 0, 0, 1.f);

    // 7. affine splits
    affine_q<<<(int)((size_t)ROWS*QD/256), 256>>>(qp, qs_gamma, qs_beta, qq, lqPh, lqPl);
    affine_k<<<(int)((size_t)ROWS*QD/256), 256>>>(qk, ks_gamma, ks_beta, qk, lk);

    // 8. lk -> lkT planes [4][128][4096]
    transcvt<<<dim3(QD/32, SEQ/32, BATCH), dim3(32,8)>>>(
        lk, lkTh, lkTl, QD, SEQ, (long long)SEQ*QD, (long long)QD*SEQ);

    // 9. sim GEMM (fp32): attn = relu(qq@qk^T/G + bias)^2
    kt_kernel<<<(int)((size_t)ROWS*QD/256), 256>>>(qk, kpT);
    sgemm<2,false,false><<<dim3(G/128, G/128, NGROUP), 256>>>(
        qq, kpT, attn, biasbuf, G, G, QD, QD, G, G,
        (long long)G*QD, (long long)G*QD, (long long)G*G, 1.f/G);

    // 10. attn -> planes
    plaincvt<<<(int)((size_t)NGROUP*G*G/256), 256>>>(attn, atPh, atPl);

    // 11. hid[:, :2048] -> vvT planes [4][2048][4096]
    transcvt<<<dim3(HID/32, SEQ/32, BATCH), dim3(32,8)>>>(
        hid, vvTh, vvTl, HID2, SEQ, (long long)SEQ*HID2, (long long)HID*SEQ);

    // 12. quad_out = attn @ cv -> acc   (per group z)
    hgemm<0,false><<<dim3(HID/128, G/128, NGROUP), 256, HG_SMEM>>>(
        atPh, atPl, vvTh, vvTl, acc, nullptr,
        G, G, SEQ, HID,
        (long long)G*G, (long long)HID*SEQ, 16, (long long)G, (long long)G*HID, 1.f);

    // 13. lin_kv = lk^T @ vv / 4096   [4][128][2048]
    hgemm<0,false><<<dim3(HID/128, 1, BATCH), 256, HG_SMEM>>>(
        lkTh, lkTl, vvTh, vvTl, linkv, nullptr,
        SEQ, SEQ, SEQ, HID,
        (long long)QD*SEQ, (long long)HID*SEQ, 1, 0, (long long)QD*HID, 1.f/SEQ);

    // 14. linkv -> linkvT planes [4][2048][128]
    transcvt<<<dim3(HID/32, QD/32, BATCH), dim3(32,8)>>>(
        linkv, kvTh, kvTl, HID, QD, (long long)QD*HID, (long long)HID*QD);

    // 15. lin_out = lq @ lin_kv, accumulate into acc
    hgemm<0,true><<<dim3(HID/128, SEQ/128, BATCH), 256, HG_SMEM>>>(
        lqPh, lqPl, kvTh, kvTl, acc, nullptr,
        QD, QD, QD, HID,
        (long long)SEQ*QD, (long long)HID*QD, 1, 0, (long long)SEQ*HID, 1.f);

    // 16. acc *= gate -> planes
    gatemul<<<(int)((size_t)ROWS*HID/256), 256>>>(acc, hid, acPh, acPl);

    // 17. out = acc @ w_out + b_out
    hgemm<0,false><<<dim3(DIM/128, ROWS/128, 1), 256, HG_SMEM>>>(
        acPh, acPl, woTh, woTl, out, b_out,
        HID, HID, HID, DIM, 0, 0, 1, 0, 0, 1.f);
}

// round 4
// speedup vs baseline: 2.5585x; 1.0155x over previous
#include <cuda_runtime.h>
#include <cuda_bf16.h>
#include <math.h>
#include <stdint.h>

#define G 256
#define BATCH 4
#define SEQ 4096
#define DIM 1024
#define HID 2048      // H
#define HID2 4096     // 2H
#define QD 128
#define ROWS (BATCH*SEQ)   // 16384
#define NGROUP (ROWS/G)    // 64

// ======================= static device scratch ==============================
__device__ float g_hid[(size_t)ROWS*HID2];          // fp32 hid (vv | gate)
__device__ float g_acc[(size_t)ROWS*HID];           // quad_out (read by lin_out epi)
__device__ float g_linkv[(size_t)BATCH*QD*HID];
__device__ float g_qp[(size_t)ROWS*QD];
__device__ float g_kp[(size_t)ROWS*QD];             // qk^T scratch
__device__ float g_qq[(size_t)ROWS*QD];
__device__ float g_qk[(size_t)ROWS*QD];
__device__ float g_lk[(size_t)ROWS*QD];
__device__ float g_attn[(size_t)NGROUP*G*G];        // fallback if out too small
__device__ float g_bias[G*G];

// bf16 hi/lo planes (16B aligned for cp.async)
__device__ __align__(16) __nv_bfloat16 g_nPh[(size_t)ROWS*DIM],  g_nPl[(size_t)ROWS*DIM];
__device__ __align__(16) __nv_bfloat16 g_qPh[(size_t)ROWS*DIM],  g_qPl[(size_t)ROWS*DIM];
__device__ __align__(16) __nv_bfloat16 g_kPh[(size_t)ROWS*DIM],  g_kPl[(size_t)ROWS*DIM];
__device__ __align__(16) __nv_bfloat16 g_whTh[(size_t)HID2*DIM], g_whTl[(size_t)HID2*DIM];
__device__ __align__(16) __nv_bfloat16 g_woTh[(size_t)DIM*HID],  g_woTl[(size_t)DIM*HID];
__device__ __align__(16) __nv_bfloat16 g_wqTh[QD*DIM], g_wqTl[QD*DIM];
__device__ __align__(16) __nv_bfloat16 g_wkTh[QD*DIM], g_wkTl[QD*DIM];
__device__ __align__(16) __nv_bfloat16 g_atPh[(size_t)NGROUP*G*G], g_atPl[(size_t)NGROUP*G*G];
__device__ __align__(16) __nv_bfloat16 g_lqPh[(size_t)ROWS*QD],  g_lqPl[(size_t)ROWS*QD];
__device__ __align__(16) __nv_bfloat16 g_lkTh[(size_t)ROWS*QD],  g_lkTl[(size_t)ROWS*QD];   // [4][128][4096]
__device__ __align__(16) __nv_bfloat16 g_vvTh[(size_t)BATCH*HID*SEQ], g_vvTl[(size_t)BATCH*HID*SEQ]; // [4][2048][4096]
__device__ __align__(16) __nv_bfloat16 g_kvTh[(size_t)BATCH*HID*QD],  g_kvTl[(size_t)BATCH*HID*QD];  // [4][2048][128]
__device__ __align__(16) __nv_bfloat16 g_acPh[(size_t)ROWS*HID], g_acPl[(size_t)ROWS*HID];

// ======================= helpers ============================================
__device__ __forceinline__ uint32_t smem_u32(const void* p) {
    uint32_t a;
    asm("{ .reg .u64 t; cvta.to.shared.u64 t, %1; cvt.u32.u64 %0, t; }" : "=r"(a) : "l"(p));
    return a;
}
__device__ __forceinline__ uint32_t lds32(uint32_t a) {
    uint32_t v;
    asm("ld.shared.b32 %0, [%1];" : "=r"(v) : "r"(a));
    return v;
}
__device__ __forceinline__ void split2(float x, __nv_bfloat16& h, __nv_bfloat16& l) {
    h = __float2bfloat16(x);
    l = __float2bfloat16(x - __bfloat162float(h));
}

#define MMA_BF16(d, a, b) \
    asm volatile("mma.sync.aligned.m16n8k16.row.col.f32.bf16.bf16.f32 " \
        "{%0,%1,%2,%3}, {%4,%5,%6,%7}, {%8,%9}, {%0,%1,%2,%3};" \
        : "+f"((d)[0]), "+f"((d)[1]), "+f"((d)[2]), "+f"((d)[3]) \
        : "r"((a)[0]), "r"((a)[1]), "r"((a)[2]), "r"((a)[3]), \
          "r"((b)[0]), "r"((b)[1]))

// ======================= HMMA bf16x3 GEMM ===================================
// C[M,N] = alpha * A @ B^T (+ col bias) (+silu / +gate-fused-split)
// A planes: [M,K] K-major bf16; B planes: [N,K] K-major bf16. K % 64 == 0.
// Per z: A += z*sA; B += (z/zdiv)*sBo + (z%zdiv)*sBi; C += z*sC; gate += z*sG.
// TN = 128 (256 thr, 8 warps) or 256 (512 thr, 16 warps). TM = 128, kc = 64.
// EPI: 0 = none, 1 = silu, 3 = planes = (mma + C) * gate  (no fp32 write)
#define PITCH 144                     // bytes per smem row (64 elem + 8 pad)
#define PLANE_A (128*PITCH)           // 18432 B

template<int RP, int NT>
__device__ __forceinline__ void load_plane(uint32_t sdst, const __nv_bfloat16* src,
                                           int row0, int ld, int k0, int tid)
{
#pragma unroll
    for (int i = 0; i < RP*8/NT; i++) {
        int idx = tid + i * NT;
        int r = idx >> 3, seg = idx & 7;
        uint32_t d = sdst + r * PITCH + seg * 16;
        const void* gp = src + (size_t)(row0 + r) * ld + k0 + seg * 8;
        asm volatile("cp.async.cg.shared.global [%0], [%1], 16;" :: "r"(d), "l"(gp));
    }
}

template<int TN, int EPI>
__global__ void __launch_bounds__(TN == 256 ? 512 : 256, 1) hgemm(
    const __nv_bfloat16* __restrict__ Ah, const __nv_bfloat16* __restrict__ Al,
    const __nv_bfloat16* __restrict__ Bh, const __nv_bfloat16* __restrict__ Bl,
    float* __restrict__ C, const float* __restrict__ bias,
    const float* __restrict__ gate, int ldg, long long sG,
    __nv_bfloat16* __restrict__ Oh, __nv_bfloat16* __restrict__ Ol,
    int K, int lda, int ldb, int ldc,
    long long sA, long long sBo, int zdiv, long long sBi, long long sC,
    float alpha)
{
    constexpr int NT = (TN == 256) ? 512 : 256;
    constexpr int PLANE_B = TN * PITCH;
    constexpr int STG = 2 * PLANE_A + 2 * PLANE_B;

    extern __shared__ char smem[];
    const int z = blockIdx.z;
    Ah += (long long)z * sA;  Al += (long long)z * sA;
    long long bo = (long long)(z / zdiv) * sBo + (long long)(z % zdiv) * sBi;
    Bh += bo;  Bl += bo;
    C  += (long long)z * sC;
    const int bm = blockIdx.y * 128, bn = blockIdx.x * TN;

    const uint32_t sb = smem_u32(smem);
    const int tid = threadIdx.x;
    const int lane = tid & 31, wid = tid >> 5;
    const int warp_m = wid & 3, warp_n = wid >> 2;    // 4 x (TN/64) warps
    const int gr = lane >> 2, tq = lane & 3;

    float acc[2][8][4];
#pragma unroll
    for (int mt = 0; mt < 2; mt++)
#pragma unroll
        for (int nt = 0; nt < 8; nt++)
#pragma unroll
            for (int i = 0; i < 4; i++) acc[mt][nt][i] = 0.f;

    const int nchunks = K >> 6;

    // prologue: stage 0
    load_plane<128, NT>(sb,                     Ah, bm, lda, 0, tid);
    load_plane<128, NT>(sb + PLANE_A,           Al, bm, lda, 0, tid);
    load_plane<TN,  NT>(sb + 2*PLANE_A,           Bh, bn, ldb, 0, tid);
    load_plane<TN,  NT>(sb + 2*PLANE_A + PLANE_B, Bl, bn, ldb, 0, tid);
    asm volatile("cp.async.commit_group;");

    for (int c = 0; c < nchunks; ++c) {
        if (c + 1 < nchunks) {
            uint32_t st = sb + ((c + 1) & 1) * STG;
            int k0 = (c + 1) << 6;
            load_plane<128, NT>(st,                     Ah, bm, lda, k0, tid);
            load_plane<128, NT>(st + PLANE_A,           Al, bm, lda, k0, tid);
            load_plane<TN,  NT>(st + 2*PLANE_A,           Bh, bn, ldb, k0, tid);
            load_plane<TN,  NT>(st + 2*PLANE_A + PLANE_B, Bl, bn, ldb, k0, tid);
            asm volatile("cp.async.commit_group;");
            asm volatile("cp.async.wait_group %0;" :: "n"(1));
        } else {
            asm volatile("cp.async.wait_group %0;" :: "n"(0));
        }
        __syncthreads();

        const uint32_t stg = sb + (c & 1) * STG;
#pragma unroll
        for (int kk = 0; kk < 4; kk++) {
            const int koff = kk * 32;   // bytes: kk*16 elems * 2
            uint32_t a_h[2][4], a_l[2][4];
#pragma unroll
            for (int mt = 0; mt < 2; mt++) {
                uint32_t ro = stg + (warp_m*32 + mt*16 + gr) * PITCH + koff + tq*4;
                a_h[mt][0] = lds32(ro);
                a_h[mt][1] = lds32(ro + 8*PITCH);
                a_h[mt][2] = lds32(ro + 16);
                a_h[mt][3] = lds32(ro + 8*PITCH + 16);
                uint32_t rl = ro + PLANE_A;
                a_l[mt][0] = lds32(rl);
                a_l[mt][1] = lds32(rl + 8*PITCH);
                a_l[mt][2] = lds32(rl + 16);
                a_l[mt][3] = lds32(rl + 8*PITCH + 16);
            }
#pragma unroll
            for (int nt = 0; nt < 8; nt++) {
                uint32_t ro = stg + 2*PLANE_A + (warp_n*64 + nt*8 + gr) * PITCH + koff + tq*4;
                uint32_t b_h[2], b_l[2];
                b_h[0] = lds32(ro);
                b_h[1] = lds32(ro + 16);
                b_l[0] = lds32(ro + PLANE_B);
                b_l[1] = lds32(ro + PLANE_B + 16);
#pragma unroll
                for (int mt = 0; mt < 2; mt++) {
                    MMA_BF16(acc[mt][nt], a_h[mt], b_h);
                    MMA_BF16(acc[mt][nt], a_h[mt], b_l);
                    MMA_BF16(acc[mt][nt], a_l[mt], b_h);
                }
            }
        }
        __syncthreads();
    }

    // epilogue
#pragma unroll
    for (int mt = 0; mt < 2; mt++) {
        const int row0 = bm + warp_m*32 + mt*16 + gr;
#pragma unroll
        for (int nt = 0; nt < 8; nt++) {
            const int col = bn + warp_n*64 + nt*8 + tq*2;
            float2 bb = make_float2(0.f, 0.f);
            if (EPI != 3 && bias) bb = *reinterpret_cast<const float2*>(bias + col);
#pragma unroll
            for (int h = 0; h < 2; h++) {
                const int row = row0 + h*8;
                float vx = acc[mt][nt][h*2+0] * alpha + bb.x;
                float vy = acc[mt][nt][h*2+1] * alpha + bb.y;
                const size_t idx = (size_t)row * ldc + col;
                if (EPI == 1) {
                    vx = vx / (1.f + expf(-vx));
                    vy = vy / (1.f + expf(-vy));
                }
                if (EPI == 3) {
                    float2 o = *reinterpret_cast<const float2*>(C + idx);
                    float2 g2 = *reinterpret_cast<const float2*>(
                        gate + (long long)z * sG + (size_t)row * ldg + col);
                    vx = (vx + o.x) * g2.x;
                    vy = (vy + o.y) * g2.y;
                    __nv_bfloat16 hx, lx, hy, ly;
                    split2(vx, hx, lx); split2(vy, hy, ly);
                    *reinterpret_cast<__nv_bfloat162*>(Oh + (long long)z * sC + idx) =
                        __nv_bfloat162(hx, hy);
                    *reinterpret_cast<__nv_bfloat162*>(Ol + (long long)z * sC + idx) =
                        __nv_bfloat162(lx, ly);
                } else {
                    *reinterpret_cast<float2*>(C + idx) = make_float2(vx, vy);
                }
            }
        }
    }
}

// ======================= elementwise / transform kernels ====================
__global__ void ln_kernel(const float* __restrict__ v, const float* __restrict__ g,
                          const float* __restrict__ b,
                          __nv_bfloat16* __restrict__ oh, __nv_bfloat16* __restrict__ ol)
{
    int row = blockIdx.x;
    const float* x = v + (size_t)row * DIM;
    int t = threadIdx.x;
    float lv[4];
    float s = 0.f;
#pragma unroll
    for (int i = 0; i < 4; i++) { lv[i] = x[t + i*256]; s += lv[i]; }
    __shared__ float red[256];
    red[t] = s; __syncthreads();
    for (int o = 128; o > 0; o >>= 1) { if (t < o) red[t] += red[t+o]; __syncthreads(); }
    float mu = red[0] * (1.f/DIM);
    __syncthreads();
    float s2 = 0.f;
#pragma unroll
    for (int i = 0; i < 4; i++) { float d = lv[i]-mu; s2 += d*d; }
    red[t] = s2; __syncthreads();
    for (int o = 128; o > 0; o >>= 1) { if (t < o) red[t] += red[t+o]; __syncthreads(); }
    float inv = rsqrtf(red[0] * (1.f/DIM) + 1e-5f);
#pragma unroll
    for (int i = 0; i < 4; i++) {
        int c = t + i*256;
        float y = (lv[i]-mu) * inv * g[c] + b[c];
        __nv_bfloat16 h, l; split2(y, h, l);
        oh[(size_t)row*DIM + c] = h;
        ol[(size_t)row*DIM + c] = l;
    }
}

__global__ void bias_kernel(const float* __restrict__ rel_emb, float* __restrict__ bias)
{
    int idx = blockIdx.x * 256 + threadIdx.x;
    int i = idx >> 8, j = idx & 255;
    int n0 = i - j;
    int ret = (n0 < 0) ? 16 : 0;
    int n = n0 < 0 ? -n0 : n0;
    int bucket;
    if (n < 8) bucket = ret + n;
    else {
        int vl = 8 + (int)(logf((float)n * 0.125f) / 2.7725887f * 8.0f);
        if (vl > 15) vl = 15;
        bucket = ret + vl;
    }
    bias[idx] = rel_emb[bucket] * 11.3137085f;
}

__global__ void plaincvt(const float* __restrict__ in,
                         __nv_bfloat16* __restrict__ oh, __nv_bfloat16* __restrict__ ol)
{
    size_t i = (size_t)blockIdx.x * 256 + threadIdx.x;
    __nv_bfloat16 h, l; split2(in[i], h, l);
    oh[i] = h; ol[i] = l;
}

// transpose fp32 [R, C] -> bf16 planes [C, R]; grid (C/32, R/32, batch), block (32, 8)
__global__ void transcvt(const float* __restrict__ in,
                         __nv_bfloat16* __restrict__ oh, __nv_bfloat16* __restrict__ ol,
                         int ld_in, int ld_out, long long sIn, long long sOut)
{
    __shared__ float t[32][33];
    in += (long long)blockIdx.z * sIn;
    oh += (long long)blockIdx.z * sOut;
    ol += (long long)blockIdx.z * sOut;
    int c0 = blockIdx.x * 32, r0 = blockIdx.y * 32;
    int tx = threadIdx.x, ty = threadIdx.y;
#pragma unroll
    for (int i = 0; i < 4; i++)
        t[ty + i*8][tx] = in[(size_t)(r0 + ty + i*8) * ld_in + c0 + tx];
    __syncthreads();
#pragma unroll
    for (int i = 0; i < 4; i++) {
        float x = t[tx][ty + i*8];
        __nv_bfloat16 h, l; split2(x, h, l);
        size_t o = (size_t)(c0 + ty + i*8) * ld_out + r0 + tx;
        oh[o] = h; ol[o] = l;
    }
}

__global__ void affine_q(const float* __restrict__ p,
                         const float* __restrict__ gamma, const float* __restrict__ beta,
                         float* __restrict__ qq,
                         __nv_bfloat16* __restrict__ lqh, __nv_bfloat16* __restrict__ lql)
{
    size_t i = (size_t)blockIdx.x * 256 + threadIdx.x;
    int c = (int)(i & (QD-1));
    float x = p[i];
    qq[i] = x * gamma[c] + beta[c];
    float lq = x * gamma[QD + c] + beta[QD + c];
    __nv_bfloat16 h, l; split2(lq, h, l);
    lqh[i] = h; lql[i] = l;
}

__global__ void affine_k(const float* __restrict__ p,
                         const float* __restrict__ gamma, const float* __restrict__ beta,
                         float* __restrict__ qk, float* __restrict__ lk)
{
    size_t i = (size_t)blockIdx.x * 256 + threadIdx.x;
    int c = (int)(i & (QD-1));
    float x = p[i];
    qk[i] = x * gamma[c] + beta[c];
    lk[i] = x * gamma[QD + c] + beta[QD + c];
}

// per-group transpose: in [64][256][128] -> out [64][128][256]
__global__ void kt_kernel(const float* __restrict__ in, float* __restrict__ qkt)
{
    size_t i = (size_t)blockIdx.x * 256 + threadIdx.x;
    size_t grp = i >> 15;
    int rem = (int)(i & 32767);
    int row = rem >> 7;
    int d   = rem & 127;
    qkt[grp * (size_t)(QD*G) + (size_t)d * G + row] = in[i];
}

// ---------------- fp32 sgemm: sim GEMM, relu^2 + 2D bias, fused plane split -
__global__ void __launch_bounds__(256) sgemm_sim(
    const float* __restrict__ A, const float* __restrict__ B,
    float* __restrict__ C, const float* __restrict__ bias,
    __nv_bfloat16* __restrict__ oh, __nv_bfloat16* __restrict__ ol,
    int K, long long sA, long long sB, long long sC, float alpha)
{
    long long z = blockIdx.z;
    A += z * sA; B += z * sB; C += z * sC;
    oh += z * sC; ol += z * sC;
    int bm = blockIdx.y * 128, bn = blockIdx.x * 128;

    __shared__ float As[8][128];
    __shared__ float Bs[8][128];
    int tid = threadIdx.x;
    int tx = tid & 15, ty = tid >> 4;

    float acc[8][8];
#pragma unroll
    for (int i = 0; i < 8; i++)
#pragma unroll
        for (int j = 0; j < 8; j++) acc[i][j] = 0.f;

    for (int k0 = 0; k0 < K; k0 += 8) {
        {
            int r = tid >> 1;
            int c = (tid & 1) << 2;
            float4 a4 = *reinterpret_cast<const float4*>(&A[(size_t)(bm + r) * QD + k0 + c]);
            As[c+0][r] = a4.x; As[c+1][r] = a4.y; As[c+2][r] = a4.z; As[c+3][r] = a4.w;
        }
        {
            int r = tid >> 5;
            int c = (tid & 31) << 2;
            float4 b4 = *reinterpret_cast<const float4*>(&B[(size_t)(k0 + r) * G + bn + c]);
            *reinterpret_cast<float4*>(&Bs[r][c]) = b4;
        }
        __syncthreads();
#pragma unroll
        for (int kk = 0; kk < 8; kk++) {
            float a[8], bb[8];
#pragma unroll
            for (int i = 0; i < 8; i++) a[i]  = As[kk][ty*8 + i];
#pragma unroll
            for (int j = 0; j < 8; j++) bb[j] = Bs[kk][tx*8 + j];
#pragma unroll
            for (int i = 0; i < 8; i++)
#pragma unroll
                for (int j = 0; j < 8; j++) acc[i][j] = fmaf(a[i], bb[j], acc[i][j]);
        }
        __syncthreads();
    }

#pragma unroll
    for (int i = 0; i < 8; i++) {
        int r = bm + ty*8 + i;
#pragma unroll
        for (int j = 0; j < 8; j++) {
            int c = bn + tx*8 + j;
            float v2 = acc[i][j] * alpha + bias[(size_t)r * G + c];
            v2 = fmaxf(v2, 0.f);
            v2 = v2 * v2;
            size_t idx = (size_t)r * G + c;
            C[idx] = v2;
            __nv_bfloat16 h, l; split2(v2, h, l);
            oh[idx] = h; ol[idx] = l;
        }
    }
}

// ======================= host orchestration =================================
static void* symaddr(const void* s) {
    void* p = nullptr;
    cudaGetSymbolAddress(&p, s);
    return p;
}

#define SM128 (2*(2*PLANE_A + 2*128*PITCH))   // 147456
#define SM256 (2*(2*PLANE_A + 2*256*PITCH))   // 221184

extern "C" void kernel_launch(void* const* d_in, const int* in_sizes, int n_in,
                              void* d_out, int out_size)
{
    const float* q       = (const float*)d_in[0];
    const float* k       = (const float*)d_in[1];
    const float* v       = (const float*)d_in[2];
    const float* ln_g    = (const float*)d_in[3];
    const float* ln_b    = (const float*)d_in[4];
    const float* w_hid   = (const float*)d_in[5];
    const float* b_hid   = (const float*)d_in[6];
    const float* w_q     = (const float*)d_in[7];
    const float* b_q     = (const float*)d_in[8];
    const float* w_k     = (const float*)d_in[9];
    const float* b_k     = (const float*)d_in[10];
    const float* qs_gamma= (const float*)d_in[11];
    const float* qs_beta = (const float*)d_in[12];
    const float* ks_gamma= (const float*)d_in[13];
    const float* ks_beta = (const float*)d_in[14];
    const float* rel_emb = (const float*)d_in[15];
    const float* w_out   = (const float*)d_in[16];
    const float* b_out   = (const float*)d_in[17];

    float* out = (float*)d_out;

    float* hid    = (float*)symaddr(g_hid);
    float* acc    = (float*)symaddr(g_acc);
    float* linkv  = (float*)symaddr(g_linkv);
    float* qp     = (float*)symaddr(g_qp);
    float* kpT    = (float*)symaddr(g_kp);
    float* qq     = (float*)symaddr(g_qq);
    float* qk     = (float*)symaddr(g_qk);
    float* lk     = (float*)symaddr(g_lk);
    float* biasbuf= (float*)symaddr(g_bias);
    float* attn_scratch = (float*)symaddr(g_attn);

    __nv_bfloat16* nPh = (__nv_bfloat16*)symaddr(g_nPh);
    __nv_bfloat16* nPl = (__nv_bfloat16*)symaddr(g_nPl);
    __nv_bfloat16* qPh = (__nv_bfloat16*)symaddr(g_qPh);
    __nv_bfloat16* qPl = (__nv_bfloat16*)symaddr(g_qPl);
    __nv_bfloat16* kPh = (__nv_bfloat16*)symaddr(g_kPh);
    __nv_bfloat16* kPl = (__nv_bfloat16*)symaddr(g_kPl);
    __nv_bfloat16* whTh = (__nv_bfloat16*)symaddr(g_whTh);
    __nv_bfloat16* whTl = (__nv_bfloat16*)symaddr(g_whTl);
    __nv_bfloat16* woTh = (__nv_bfloat16*)symaddr(g_woTh);
    __nv_bfloat16* woTl = (__nv_bfloat16*)symaddr(g_woTl);
    __nv_bfloat16* wqTh = (__nv_bfloat16*)symaddr(g_wqTh);
    __nv_bfloat16* wqTl = (__nv_bfloat16*)symaddr(g_wqTl);
    __nv_bfloat16* wkTh = (__nv_bfloat16*)symaddr(g_wkTh);
    __nv_bfloat16* wkTl = (__nv_bfloat16*)symaddr(g_wkTl);
    __nv_bfloat16* atPh = (__nv_bfloat16*)symaddr(g_atPh);
    __nv_bfloat16* atPl = (__nv_bfloat16*)symaddr(g_atPl);
    __nv_bfloat16* lqPh = (__nv_bfloat16*)symaddr(g_lqPh);
    __nv_bfloat16* lqPl = (__nv_bfloat16*)symaddr(g_lqPl);
    __nv_bfloat16* lkTh = (__nv_bfloat16*)symaddr(g_lkTh);
    __nv_bfloat16* lkTl = (__nv_bfloat16*)symaddr(g_lkTl);
    __nv_bfloat16* vvTh = (__nv_bfloat16*)symaddr(g_vvTh);
    __nv_bfloat16* vvTl = (__nv_bfloat16*)symaddr(g_vvTl);
    __nv_bfloat16* kvTh = (__nv_bfloat16*)symaddr(g_kvTh);
    __nv_bfloat16* kvTl = (__nv_bfloat16*)symaddr(g_kvTl);
    __nv_bfloat16* acPh = (__nv_bfloat16*)symaddr(g_acPh);
    __nv_bfloat16* acPl = (__nv_bfloat16*)symaddr(g_acPl);

    const long long OUT0 = (long long)ROWS * DIM;
    const long long OUT1 = (long long)NGROUP * G * G;
    float* attn = (out_size >= OUT0 + OUT1) ? (out + OUT0) : attn_scratch;

    cudaFuncSetAttribute(hgemm<128,1>, cudaFuncAttributeMaxDynamicSharedMemorySize, SM128);
    cudaFuncSetAttribute(hgemm<256,0>, cudaFuncAttributeMaxDynamicSharedMemorySize, SM256);
    cudaFuncSetAttribute(hgemm<256,1>, cudaFuncAttributeMaxDynamicSharedMemorySize, SM256);
    cudaFuncSetAttribute(hgemm<256,3>, cudaFuncAttributeMaxDynamicSharedMemorySize, SM256);

    // 1. LN(v) -> normed planes
    ln_kernel<<<ROWS, 256>>>(v, ln_g, ln_b, nPh, nPl);
    // 2. T5 bias
    bias_kernel<<<G*G/256, 256>>>(rel_emb, biasbuf);
    // 3. convert q, k inputs to planes
    plaincvt<<<(int)((size_t)ROWS*DIM/256), 256>>>(q, qPh, qPl);
    plaincvt<<<(int)((size_t)ROWS*DIM/256), 256>>>(k, kPh, kPl);
    // 4. transpose+convert weights: [K,N] -> [N,K]
    transcvt<<<dim3(HID2/32, DIM/32, 1), dim3(32,8)>>>(w_hid, whTh, whTl, HID2, DIM, 0, 0);
    transcvt<<<dim3(DIM/32, HID/32, 1), dim3(32,8)>>>(w_out, woTh, woTl, DIM, HID, 0, 0);
    transcvt<<<dim3(QD/32, DIM/32, 1), dim3(32,8)>>>(w_q, wqTh, wqTl, QD, DIM, 0, 0);
    transcvt<<<dim3(QD/32, DIM/32, 1), dim3(32,8)>>>(w_k, wkTh, wkTl, QD, DIM, 0, 0);

    // 5. hid = silu(normed @ w_hid + b_hid)   [16384 x 4096]
    hgemm<256,1><<<dim3(HID2/256, ROWS/128, 1), 512, SM256>>>(
        nPh, nPl, whTh, whTl, hid, b_hid, nullptr, 0, 0, nullptr, nullptr,
        DIM, DIM, DIM, HID2, 0, 0, 1, 0, 0, 1.f);

    // 6. qp = silu(q @ w_q + b_q); kp = silu(k @ w_k + b_k)   (N = 128)
    hgemm<128,1><<<dim3(1, ROWS/128, 1), 256, SM128>>>(
        qPh, qPl, wqTh, wqTl, qp, b_q, nullptr, 0, 0, nullptr, nullptr,
        DIM, DIM, DIM, QD, 0, 0, 1, 0, 0, 1.f);
    hgemm<128,1><<<dim3(1, ROWS/128, 1), 256, SM128>>>(
        kPh, kPl, wkTh, wkTl, qk /*temp kp*/, b_k, nullptr, 0, 0, nullptr, nullptr,
        DIM, DIM, DIM, QD, 0, 0, 1, 0, 0, 1.f);

    // 7. affine splits
    affine_q<<<(int)((size_t)ROWS*QD/256), 256>>>(qp, qs_gamma, qs_beta, qq, lqPh, lqPl);
    affine_k<<<(int)((size_t)ROWS*QD/256), 256>>>(qk, ks_gamma, ks_beta, qk, lk);

    // 8. lk -> lkT planes [4][128][4096]
    transcvt<<<dim3(QD/32, SEQ/32, BATCH), dim3(32,8)>>>(
        lk, lkTh, lkTl, QD, SEQ, (long long)SEQ*QD, (long long)QD*SEQ);

    // 9. sim GEMM (fp32): attn = relu(qq@qk^T/G + bias)^2, fused plane split
    kt_kernel<<<(int)((size_t)ROWS*QD/256), 256>>>(qk, kpT);
    sgemm_sim<<<dim3(G/128, G/128, NGROUP), 256>>>(
        qq, kpT, attn, biasbuf, atPh, atPl,
        QD, (long long)G*QD, (long long)G*QD, (long long)G*G, 1.f/G);

    // 10. hid[:, :2048] -> vvT planes [4][2048][4096]
    transcvt<<<dim3(HID/32, SEQ/32, BATCH), dim3(32,8)>>>(
        hid, vvTh, vvTl, HID2, SEQ, (long long)SEQ*HID2, (long long)HID*SEQ);

    // 11. quad_out = attn @ cv -> acc   (per group z)
    hgemm<256,0><<<dim3(HID/256, G/128, NGROUP), 512, SM256>>>(
        atPh, atPl, vvTh, vvTl, acc, nullptr, nullptr, 0, 0, nullptr, nullptr,
        G, G, SEQ, HID,
        (long long)G*G, (long long)HID*SEQ, 16, (long long)G, (long long)G*HID, 1.f);

    // 12. lin_kv = lk^T @ vv / 4096   [4][128][2048]
    hgemm<256,0><<<dim3(HID/256, 1, BATCH), 512, SM256>>>(
        lkTh, lkTl, vvTh, vvTl, linkv, nullptr, nullptr, 0, 0, nullptr, nullptr,
        SEQ, SEQ, SEQ, HID,
        (long long)QD*SEQ, (long long)HID*SEQ, 1, 0, (long long)QD*HID, 1.f/SEQ);

    // 13. linkv -> linkvT planes [4][2048][128]
    transcvt<<<dim3(HID/32, QD/32, BATCH), dim3(32,8)>>>(
        linkv, kvTh, kvTl, HID, QD, (long long)QD*HID, (long long)HID*QD);

    // 14. lin_out + quad_out(acc) fused: planes = (lq@lin_kv + acc) * gate
    hgemm<256,3><<<dim3(HID/256, SEQ/128, BATCH), 512, SM256>>>(
        lqPh, lqPl, kvTh, kvTl, acc, nullptr,
        hid + HID, HID2, (long long)SEQ*HID2, acPh, acPl,
        QD, QD, QD, HID,
        (long long)SEQ*QD, (long long)HID*QD, 1, 0, (long long)SEQ*HID, 1.f);

    // 15. out = acc_planes @ w_out + b_out
    hgemm<256,0><<<dim3(DIM/256, ROWS/128, 1), 512, SM256>>>(
        acPh, acPl, woTh, woTl, out, b_out, nullptr, 0, 0, nullptr, nullptr,
        HID, HID, HID, DIM, 0, 0, 1, 0, 0, 1.f);
}